// round 14
// baseline (speedup 1.0000x reference)
#include <cuda_runtime.h>
#include <cstdint>

// Bilateral filter: B=8, C=3, H=W=512, K=5, sigma_s=2.0, sigma_r=0.1
//
// R14: R12 compute body (1-warp CTA, 4x4 patch/thread, 294 shared-exp
// pairs, baked log2-spatial immediates, batched-RCP epilogue) + cp.async
// TWO-TILE PIPELINE: each CTA loads 2 tiles into double-buffered smem via
// LDGSTS (no dest regs), computes tile0 while tile1's loads land. Halves
// the per-CTA global-load latency exposure that kept MUFU at 83%.
// smem holds RAW values; the C1 scale moves to the register row-loads
// (FMUL-imm, rt=1). Vertical reflect = per-row source remap in the
// cp.async path; horizontal-edge tiles (bxT in {0,15}) use a scalar path.

#define HW   512
#define SROW 36
#define TILEF (20 * SROW)       // 720 floats per tile buffer
#define C1F  8.4932165750422091f
#define LSOF(dsq) (-0.18033688011112043f * (float)(dsq))   // log2(exp(-dsq/8))

__device__ __forceinline__ float ex2a(float v) {
    float y;
    asm("ex2.approx.ftz.f32 %0, %1;" : "=f"(y) : "f"(v));
    return y;
}
__device__ __forceinline__ float rcpa(float v) {
    float y;
    asm("rcp.approx.ftz.f32 %0, %1;" : "=f"(y) : "f"(v));
    return y;
}
__device__ __forceinline__ uint32_t smem_u32(const void* p) {
    uint32_t a;
    asm("{ .reg .u64 t; cvta.to.shared.u64 t, %1; cvt.u32.u64 %0, t; }"
        : "=r"(a) : "l"(p));
    return a;
}
__device__ __forceinline__ void cp8(uint32_t s, const float* g) {
    asm volatile("cp.async.ca.shared.global [%0], [%1], 8;" :: "r"(s), "l"(g));
}
#define CP_COMMIT() asm volatile("cp.async.commit_group;" ::: "memory")
#define CP_WAIT1()  asm volatile("cp.async.wait_group 1;" ::: "memory")
#define CP_WAIT0()  asm volatile("cp.async.wait_group 0;" ::: "memory")

__device__ __forceinline__ int reflect512(int g) {
    g = (g < 0) ? -g : g;
    return (g > 511) ? (1022 - g) : g;
}

// ownership of a window-local coordinate (window is 8x8, owned core is 2..5)
#define OWN(rr,cc) ((rr) >= 2 && (rr) <= 5 && (cc) >= 2 && (cc) <= 5)

#define PAIR(va, vb, ra, ca, rb, cb, di, dj) do {                              \
    const bool oa_ = OWN(ra, ca), ob_ = OWN(rb, cb);                           \
    if (oa_ || ob_) {                                                          \
        float t_ = (va) - (vb);                                                \
        float w_ = ex2a(fmaf(t_, -t_, LSOF((di)*(di)+(dj)*(dj))));             \
        if (oa_) { const int ia_ = ((ra)-2)*4 + ((ca)-2);                      \
                   wsum[ia_] += w_; acc[ia_] = fmaf(w_, (vb), acc[ia_]); }     \
        if (ob_) { const int ib_ = ((rb)-2)*4 + ((cb)-2);                      \
                   wsum[ib_] += w_; acc[ib_] = fmaf(w_, (va), acc[ib_]); }     \
    }                                                                          \
} while (0)

// Issue the loads for tile t into buf (raw values, no scale).
// cp.async path for non-horizontal-edge tiles (vertical reflect via row
// remap); scalar LDG/STS path for bxT in {0,15}.
__device__ __forceinline__ void load_tile(uint32_t sbuf, float* buf,
                                          const float* __restrict__ x,
                                          int t, int tid) {
    const int bxT = t & 15;
    const int byT = (t >> 4) & 31;
    const int z   = t >> 9;
    const int bx  = bxT * 32;
    const int by  = byT * 16;
    const float* __restrict__ src = x + (size_t)z * (HW * HW);

    if (bxT != 0 && bxT != 15) {
        // 20 rows x 36 cols = 360 float2 chunks (8B aligned: (bx-2)*4 % 8 == 0)
        #pragma unroll
        for (int it = 0; it < 12; it++) {
            const int idx = it * 32 + tid;
            if (idx < 360) {
                const int r = idx / 18;
                const int c = idx - r * 18;        // float2 chunk in row
                const int gr = reflect512(by + r - 2);
                cp8(sbuf + (uint32_t)(r * SROW + c * 2) * 4u,
                    src + (size_t)gr * HW + (bx - 2) + c * 2);
            }
        }
    } else {
        for (int i = tid; i < 20 * 36; i += 32) {
            const int r = i / 36;
            const int c = i - r * 36;
            buf[r * SROW + c] = src[(size_t)reflect512(by + r - 2) * HW +
                                    reflect512(bx + c - 2)];
        }
    }
    CP_COMMIT();
}

__device__ __forceinline__ void compute_tile(const float* __restrict__ tile,
                                             float* __restrict__ out,
                                             int t, int tid) {
    const int bx = (t & 15) * 32;
    const int by = ((t >> 4) & 31) * 16;
    const int z  = t >> 9;
    float* __restrict__ dst = out + (size_t)z * (HW * HW);

    const int R0 = 4 * (tid >> 3);   // 0,4,8,12
    const int C0 = 4 * (tid & 7);    // 0..28

    float wsum[16], acc[16];
    #pragma unroll
    for (int i = 0; i < 16; i++) { wsum[i] = 0.0f; acc[i] = 0.0f; }

    float rows[2][8];   // 2-row ping-pong ring

    #pragma unroll
    for (int r = 0; r < 8; r++) {
        const int cr = r & 1;

        {   // scale-at-register-load (smem holds raw values)
            float4 a = *(const float4*)&tile[(R0 + r) * SROW + C0];
            float4 b = *(const float4*)&tile[(R0 + r) * SROW + C0 + 4];
            rows[cr][0] = a.x * C1F; rows[cr][1] = a.y * C1F;
            rows[cr][2] = a.z * C1F; rows[cr][3] = a.w * C1F;
            rows[cr][4] = b.x * C1F; rows[cr][5] = b.y * C1F;
            rows[cr][6] = b.z * C1F; rows[cr][7] = b.w * C1F;
        }

        // ---- center taps: weight exactly 1.0, no exp
        if (r >= 2 && r <= 5) {
            #pragma unroll
            for (int c = 2; c <= 5; c++) {
                const int ia = (r - 2) * 4 + (c - 2);
                wsum[ia] += 1.0f;
                acc[ia]  += rows[cr][c];
            }
        }

        // ---- di=0 pairs
        if (r >= 2 && r <= 5) {
            #pragma unroll
            for (int c = 1; c <= 5; c++)
                PAIR(rows[cr][c], rows[cr][c+1], r, c, r, c+1, 0, 1);
            #pragma unroll
            for (int c = 0; c <= 5; c++)
                PAIR(rows[cr][c], rows[cr][c+2], r, c, r, c+2, 0, 2);
        }

        // ---- di=1 pairs from the ring
        if (r >= 1) {
            const int pr = (r - 1) & 1;
            #pragma unroll
            for (int dj = -2; dj <= 2; dj++) {
                #pragma unroll
                for (int c = 0; c < 8; c++) {
                    const int cb = c + dj;
                    if (cb < 0 || cb > 7) continue;
                    PAIR(rows[pr][c], rows[cr][cb], r-1, c, r, cb, 1, dj);
                }
            }
        }

        // ---- di=2 pairs: partner row r-2 re-read from smem (transient)
        if (r >= 2) {
            float p2[8];
            {
                float4 a = *(const float4*)&tile[(R0 + r - 2) * SROW + C0];
                float4 b = *(const float4*)&tile[(R0 + r - 2) * SROW + C0 + 4];
                p2[0] = a.x * C1F; p2[1] = a.y * C1F;
                p2[2] = a.z * C1F; p2[3] = a.w * C1F;
                p2[4] = b.x * C1F; p2[5] = b.y * C1F;
                p2[6] = b.z * C1F; p2[7] = b.w * C1F;
            }
            #pragma unroll
            for (int dj = -2; dj <= 2; dj++) {
                #pragma unroll
                for (int c = 0; c < 8; c++) {
                    const int cb = c + dj;
                    if (cb < 0 || cb > 7) continue;
                    PAIR(p2[c], rows[cr][cb], r-2, c, r, cb, 2, dj);
                }
            }
        }
    }

    // ---- normalize: batched reciprocal, 1/C1 folded
    const float INV = 1.0f / C1F;
    float invw[16];
    #pragma unroll
    for (int g = 0; g < 2; g++) {
        const float* w = wsum + g * 8;
        float* iw = invw + g * 8;
        float p01 = w[0] * w[1], p23 = w[2] * w[3];
        float p45 = w[4] * w[5], p67 = w[6] * w[7];
        float p0123 = p01 * p23, p4567 = p45 * p67;
        float R = rcpa(p0123 * p4567) * INV;
        float r0123 = R * p4567, r4567 = R * p0123;
        float r01 = r0123 * p23, r23 = r0123 * p01;
        float r45 = r4567 * p67, r67 = r4567 * p45;
        iw[0] = r01 * w[1];  iw[1] = r01 * w[0];
        iw[2] = r23 * w[3];  iw[3] = r23 * w[2];
        iw[4] = r45 * w[5];  iw[5] = r45 * w[4];
        iw[6] = r67 * w[7];  iw[7] = r67 * w[6];
    }

    #pragma unroll
    for (int pr = 0; pr < 4; pr++) {
        float4 o;
        o.x = acc[pr*4 + 0] * invw[pr*4 + 0];
        o.y = acc[pr*4 + 1] * invw[pr*4 + 1];
        o.z = acc[pr*4 + 2] * invw[pr*4 + 2];
        o.w = acc[pr*4 + 3] * invw[pr*4 + 3];
        *(float4*)&dst[(by + R0 + pr) * HW + bx + C0] = o;
    }
}

__global__ __launch_bounds__(32, 32)
void bilateral_kernel(const float* __restrict__ x,
                      float* __restrict__ out) {
    __shared__ __align__(16) float buf[2][TILEF];

    const int tid = threadIdx.x;
    const int t0  = blockIdx.x;
    const int t1  = blockIdx.x + 6144;

    const uint32_t s0 = smem_u32(buf[0]);
    const uint32_t s1 = smem_u32(buf[1]);

    load_tile(s0, buf[0], x, t0, tid);   // group 0
    load_tile(s1, buf[1], x, t1, tid);   // group 1

    CP_WAIT1();           // tile0 landed
    __syncwarp();
    compute_tile(buf[0], out, t0, tid);  // tile1 loads hide behind this

    CP_WAIT0();           // tile1 landed
    __syncwarp();
    compute_tile(buf[1], out, t1, tid);
}

extern "C" void kernel_launch(void* const* d_in, const int* in_sizes, int n_in,
                              void* d_out, int out_size) {
    const float* x = (const float*)d_in[0];  // (8,3,512,512)
    float* out     = (float*)d_out;

    bilateral_kernel<<<6144, 32>>>(x, out);  // 2 tiles per CTA, 12288 tiles
}

// round 15
// speedup vs baseline: 1.3171x; 1.3171x over previous
#include <cuda_runtime.h>

// Bilateral filter: B=8, C=3, H=W=512, K=5, sigma_s=2.0, sigma_r=0.1
//
// FINAL (== R12, best measured 31.2us):
//  - Pairwise weight sharing: w(p,q) = spatial(d)*exp(-50(xp-xq)^2) is
//    symmetric, so one EX2 feeds both owned endpoints. 4x4 pixel patch per
//    thread -> 294 unique EX2 per 16 px (18.4/px vs 25/px naive), center
//    tap exp-free.
//  - spatial = exp(-d^2/8) exactly -> log2-spatial baked as immediates;
//    tile pre-scaled by C1 = sqrt(50*log2 e) so each pair is FADD+FFMA+EX2.
//  - 1-warp CTAs (32 thr) on 32x16 tiles, 32 CTAs/SM (64 regs x 32 x 32 =
//    64K exactly), __syncwarp barriers, finest work-steal backfill grain.
//  - di=1 partner row via 2-row register ring; di=2 via transient smem
//    re-read (LDS pipe idle); batched-RCP epilogue (2 RCP/thread).
// Measured: MUFU (EX2) ~83% of elapsed = the binding pipe. Exp-substitution
// (f16x2, polynomial) and latency-pipelining (persistent, cp.async)
// alternatives all measured slower in R4/R11/R13/R14.

#define HW   512
#define TILEW 32
#define TILEH 16
#define SROW 36
#define C1F  8.4932165750422091f
#define LSOF(dsq) (-0.18033688011112043f * (float)(dsq))   // log2(exp(-dsq/8))

__device__ __forceinline__ float ex2a(float v) {
    float y;
    asm("ex2.approx.ftz.f32 %0, %1;" : "=f"(y) : "f"(v));
    return y;
}

__device__ __forceinline__ float rcpa(float v) {
    float y;
    asm("rcp.approx.ftz.f32 %0, %1;" : "=f"(y) : "f"(v));
    return y;
}

__device__ __forceinline__ int reflect512(int g) {
    g = (g < 0) ? -g : g;
    return (g > 511) ? (1022 - g) : g;
}

// ownership of a window-local coordinate (window is 8x8, owned core is 2..5)
#define OWN(rr,cc) ((rr) >= 2 && (rr) <= 5 && (cc) >= 2 && (cc) <= 5)

// one unordered pair; all index args compile-time constants after unrolling
#define PAIR(va, vb, ra, ca, rb, cb, di, dj) do {                              \
    const bool oa_ = OWN(ra, ca), ob_ = OWN(rb, cb);                           \
    if (oa_ || ob_) {                                                          \
        float t_ = (va) - (vb);                                                \
        float w_ = ex2a(fmaf(t_, -t_, LSOF((di)*(di)+(dj)*(dj))));             \
        if (oa_) { const int ia_ = ((ra)-2)*4 + ((ca)-2);                      \
                   wsum[ia_] += w_; acc[ia_] = fmaf(w_, (vb), acc[ia_]); }     \
        if (ob_) { const int ib_ = ((rb)-2)*4 + ((cb)-2);                      \
                   wsum[ib_] += w_; acc[ib_] = fmaf(w_, (va), acc[ib_]); }     \
    }                                                                          \
} while (0)

__global__ __launch_bounds__(32, 32)
void bilateral_kernel(const float* __restrict__ x,
                      float* __restrict__ out) {
    __shared__ float tile[20 * SROW];   // 16+4 rows x 36 cols

    const int bxT = blockIdx.x;              // 0..15
    const int byT = blockIdx.y;              // 0..31
    const int bx  = bxT * TILEW;
    const int by  = byT * TILEH;
    const float* __restrict__ src = x   + (size_t)blockIdx.z * (HW * HW);
    float* __restrict__       dst = out + (size_t)blockIdx.z * (HW * HW);

    const int tid = threadIdx.x;             // 0..31

    const bool interior = (bxT != 0) && (bxT != 15) &&
                          (byT != 0) && (byT != 31);

    if (interior) {
        const float* base = src + (size_t)(by - 2) * HW + (bx - 2);
        // main region: 20 rows x cols 0..31 (one col per lane)
        #pragma unroll
        for (int r = 0; r < 20; r++) {
            tile[r * SROW + tid] = base[r * HW + tid] * C1F;
        }
        // strip: cols 32..35, 20 rows (80 elems, 3 guarded passes of 32)
        #pragma unroll
        for (int it = 0; it < 3; it++) {
            const int idx = it * 32 + tid;
            if (idx < 80) {
                const int r = idx >> 2;
                const int c = 32 + (idx & 3);
                tile[r * SROW + c] = base[r * HW + c] * C1F;
            }
        }
    } else {
        for (int i = tid; i < 20 * 36; i += 32) {
            const int r = i / 36;
            const int c = i - r * 36;
            tile[r * SROW + c] = src[reflect512(by + r - 2) * HW +
                                     reflect512(bx + c - 2)] * C1F;
        }
    }
    __syncwarp();

    const int R0 = 4 * (tid >> 3);   // smem row of window origin (0,4,8,12)
    const int C0 = 4 * (tid & 7);    // smem col of window origin (0..28)

    float wsum[16], acc[16];
    #pragma unroll
    for (int i = 0; i < 16; i++) { wsum[i] = 0.0f; acc[i] = 0.0f; }

    float rows[2][8];   // 2-row ping-pong ring (constant indices after unroll)

    #pragma unroll
    for (int r = 0; r < 8; r++) {
        const int cr = r & 1;

        // load window row r: cols C0..C0+7, two aligned float4 (conflict-free)
        {
            float4 a = *(const float4*)&tile[(R0 + r) * SROW + C0];
            float4 b = *(const float4*)&tile[(R0 + r) * SROW + C0 + 4];
            rows[cr][0] = a.x; rows[cr][1] = a.y;
            rows[cr][2] = a.z; rows[cr][3] = a.w;
            rows[cr][4] = b.x; rows[cr][5] = b.y;
            rows[cr][6] = b.z; rows[cr][7] = b.w;
        }

        // ---- center taps: weight is exactly 1.0, no exp
        if (r >= 2 && r <= 5) {
            #pragma unroll
            for (int c = 2; c <= 5; c++) {
                const int ia = (r - 2) * 4 + (c - 2);
                wsum[ia] += 1.0f;
                acc[ia]  += rows[cr][c];
            }
        }

        // ---- di=0 pairs (within row r)
        if (r >= 2 && r <= 5) {
            #pragma unroll
            for (int c = 1; c <= 5; c++)       // dj = 1
                PAIR(rows[cr][c], rows[cr][c+1], r, c, r, c+1, 0, 1);
            #pragma unroll
            for (int c = 0; c <= 5; c++)       // dj = 2
                PAIR(rows[cr][c], rows[cr][c+2], r, c, r, c+2, 0, 2);
        }

        // ---- di=1 pairs: rows (r-1, r) from the ring
        if (r >= 1) {
            const int pr = (r - 1) & 1;
            #pragma unroll
            for (int dj = -2; dj <= 2; dj++) {
                #pragma unroll
                for (int c = 0; c < 8; c++) {
                    const int cb = c + dj;
                    if (cb < 0 || cb > 7) continue;
                    PAIR(rows[pr][c], rows[cr][cb], r-1, c, r, cb, 1, dj);
                }
            }
        }

        // ---- di=2 pairs: partner row r-2 re-read from smem (transient regs)
        if (r >= 2) {
            float p2[8];
            {
                float4 a = *(const float4*)&tile[(R0 + r - 2) * SROW + C0];
                float4 b = *(const float4*)&tile[(R0 + r - 2) * SROW + C0 + 4];
                p2[0] = a.x; p2[1] = a.y; p2[2] = a.z; p2[3] = a.w;
                p2[4] = b.x; p2[5] = b.y; p2[6] = b.z; p2[7] = b.w;
            }
            #pragma unroll
            for (int dj = -2; dj <= 2; dj++) {
                #pragma unroll
                for (int c = 0; c < 8; c++) {
                    const int cb = c + dj;
                    if (cb < 0 || cb > 7) continue;
                    PAIR(p2[c], rows[cr][cb], r-2, c, r, cb, 2, dj);
                }
            }
        }
    }

    // ---- normalize: batched reciprocal (2 RCP per thread), INV folded
    const float INV = 1.0f / C1F;
    float invw[16];
    #pragma unroll
    for (int g = 0; g < 2; g++) {
        const float* w = wsum + g * 8;
        float* iw = invw + g * 8;
        float p01 = w[0] * w[1], p23 = w[2] * w[3];
        float p45 = w[4] * w[5], p67 = w[6] * w[7];
        float p0123 = p01 * p23, p4567 = p45 * p67;
        float R = rcpa(p0123 * p4567) * INV;
        float r0123 = R * p4567, r4567 = R * p0123;
        float r01 = r0123 * p23, r23 = r0123 * p01;
        float r45 = r4567 * p67, r67 = r4567 * p45;
        iw[0] = r01 * w[1];  iw[1] = r01 * w[0];
        iw[2] = r23 * w[3];  iw[3] = r23 * w[2];
        iw[4] = r45 * w[5];  iw[5] = r45 * w[4];
        iw[6] = r67 * w[7];  iw[7] = r67 * w[6];
    }

    #pragma unroll
    for (int pr = 0; pr < 4; pr++) {
        float4 o;
        o.x = acc[pr*4 + 0] * invw[pr*4 + 0];
        o.y = acc[pr*4 + 1] * invw[pr*4 + 1];
        o.z = acc[pr*4 + 2] * invw[pr*4 + 2];
        o.w = acc[pr*4 + 3] * invw[pr*4 + 3];
        *(float4*)&dst[(by + R0 + pr) * HW + bx + C0] = o;
    }
}

extern "C" void kernel_launch(void* const* d_in, const int* in_sizes, int n_in,
                              void* d_out, int out_size) {
    const float* x = (const float*)d_in[0];  // (8,3,512,512)
    float* out     = (float*)d_out;

    dim3 block(32);
    dim3 grid(HW / TILEW, HW / TILEH, 24);   // 16 x 32 x 24 = 12288 CTAs
    bilateral_kernel<<<grid, block>>>(x, out);
}